// round 13
// baseline (speedup 1.0000x reference)
#include <cuda_runtime.h>
#include <math.h>
#include <stdint.h>

#define B 8
#define S 2048
#define I_IN 8
#define H 256
#define NC 16       // CTAs per batch
#define CHUNK 16    // h outputs per CTA per layer
#define NT 256
#define NSPLIT 8
#define SC (S / NSPLIT)   // 256
#define CANARY 0x7FC00001u

// ---------------- device scratch ----------------
__device__ float g_hs0[(size_t)B * S * H];
__device__ float g_hs1[(size_t)B * S * H];
__device__ float g_pm[B * 4 * NSPLIT];
__device__ float g_ps[B * 4 * NSPLIT];
__device__ float g_ph[B * 4 * NSPLIT * H];

__device__ __forceinline__ float fsig_(float x)  { return 1.f / (1.f + __expf(-x)); }
__device__ __forceinline__ float ftanh_(float x) { return 2.f / (1.f + __expf(-2.f * x)) - 1.f; }

__device__ __forceinline__ uint64_t fma2_(uint64_t a, uint64_t b, uint64_t c) {
    uint64_t d;
    asm("fma.rn.f32x2 %0, %1, %2, %3;" : "=l"(d) : "l"(a), "l"(b), "l"(c));
    return d;
}
__device__ __forceinline__ float hsum2_(uint64_t v) {
    return __uint_as_float((uint32_t)v) + __uint_as_float((uint32_t)(v >> 32));
}
__device__ __forceinline__ uint32_t ldg_relaxed_u32(const uint32_t* p) {
    uint32_t v;
    asm volatile("ld.relaxed.gpu.global.b32 %0, [%1];" : "=r"(v) : "l"(p) : "memory");
    return v;
}
__device__ __forceinline__ void stg_relaxed_u32(uint32_t* p, uint32_t v) {
    asm volatile("st.relaxed.gpu.global.b32 [%0], %1;" :: "l"(p), "r"(v) : "memory");
}

// ---------------- canary fill -----------------------------------------------------
__global__ void fill_kernel() {
    const uint4 c = make_uint4(CANARY, CANARY, CANARY, CANARY);
    const size_t n4 = (size_t)B * S * H / 4;
    uint4* p0 = reinterpret_cast<uint4*>(g_hs0);
    uint4* p1 = reinterpret_cast<uint4*>(g_hs1);
    for (size_t i = (size_t)blockIdx.x * blockDim.x + threadIdx.x; i < n4;
         i += (size_t)gridDim.x * blockDim.x) {
        p0[i] = c; p1[i] = c;
    }
}

__global__ void dummy_kernel() {}

// ---------------- fused 2-layer LSTM: one tick = layer0(t) + layer1(t-1) ----------
// Value-based L2 sync (canary). One poll stage per tick serves both layers:
//   tick t polls h0(t-1) [input to L0(t) AND L1(t-1)] and h1(t-2) [recurrent L1].
// Owners: warp0 lanes 0-15 -> layer0 cell; warp1 lanes 0-15 (tid 32-47) -> layer1.
__global__ void __launch_bounds__(NT, 1) lstm_fused_kernel(
    const float* __restrict__ xin,
    const float* __restrict__ w_ih0, const float* __restrict__ w_hh0,
    const float* __restrict__ b_ih0, const float* __restrict__ b_hh0,
    const float* __restrict__ w_ih1, const float* __restrict__ w_hh1,
    const float* __restrict__ b_ih1, const float* __restrict__ b_hh1)
{
    const int r   = blockIdx.x;
    const int b   = blockIdx.y;
    const int tid = threadIdx.x;
    const int s   = tid >> 6;          // 64-wide segment of the 256-dot
    const int gL  = tid & 63;
    const int q   = gL >> 4;
    const int j   = gL & 15;
    const int row = q * H + r * CHUNK + j;   // same row id used for both layers

    __shared__ alignas(16) float sh_h0[H];       // h0(t-1)
    __shared__ alignas(16) float sh_h1[H];       // h1(t-2)
    __shared__ alignas(16) float sh_x[I_IN];     // x(t), 8 wide
    __shared__ float sh_part0[4 * 64];
    __shared__ float sh_part1[4 * 64];

    // ---- register-resident packed weights (both layers) ----
    uint64_t whh0[32], whh1[32], wih1[32], wih0[4];
    {
        const uint64_t* p = reinterpret_cast<const uint64_t*>(w_hh0) + ((row * H + s * 64) >> 1);
#pragma unroll
        for (int k = 0; k < 32; k++) whh0[k] = p[k];
    }
    {
        const uint64_t* p = reinterpret_cast<const uint64_t*>(w_hh1) + ((row * H + s * 64) >> 1);
#pragma unroll
        for (int k = 0; k < 32; k++) whh1[k] = p[k];
    }
    {
        const uint64_t* p = reinterpret_cast<const uint64_t*>(w_ih1) + ((row * H + s * 64) >> 1);
#pragma unroll
        for (int k = 0; k < 32; k++) wih1[k] = p[k];
    }
    {
        const uint64_t* p = reinterpret_cast<const uint64_t*>(w_ih0) + ((row * I_IN) >> 1);
#pragma unroll
        for (int k = 0; k < 4; k++) wih0[k] = (s == 0) ? p[k] : 0ull;
    }

    // owner biases: tid<16 -> layer0 (j=tid); 32<=tid<48 -> layer1 (j=tid-32)
    float bias_q[4];
    if (tid < CHUNK) {
#pragma unroll
        for (int qq = 0; qq < 4; qq++) {
            int rr = qq * H + r * CHUNK + tid;
            bias_q[qq] = b_ih0[rr] + b_hh0[rr];
        }
    } else if (tid >= 32 && tid < 32 + CHUNK) {
#pragma unroll
        for (int qq = 0; qq < 4; qq++) {
            int rr = qq * H + r * CHUNK + (tid - 32);
            bias_q[qq] = b_ih1[rr] + b_hh1[rr];
        }
    }

    const float* xb = xin + (size_t)b * S * I_IN;
    uint32_t* hs0_u = reinterpret_cast<uint32_t*>(g_hs0) + (size_t)b * S * H;
    uint32_t* hs1_u = reinterpret_cast<uint32_t*>(g_hs1) + (size_t)b * S * H;

    if (tid < H) { sh_h0[tid] = 0.f; sh_h1[tid] = 0.f; }
    if (tid < I_IN) sh_x[tid] = 0.f;

    float xreg = (tid < I_IN) ? xb[tid] : 0.f;

    float c0 = 0.f;   // layer0 cell (tid<16)
    float c1 = 0.f;   // layer1 cell (tid 32..47)

    for (int t = 0; t <= S; t++) {
        // ---- stage x(t) (layer0); prefetch x(t+1) ----
        if (tid < I_IN && t < S) {
            sh_x[tid] = xreg;
            int tn = (t + 1 < S) ? t + 1 : t;
            xreg = xb[tn * I_IN + tid];
        }
        // ---- combined poll: h0(t-1) and h1(t-2), one shared L2 latency ----
        if (t >= 1) {
            const uint32_t* p0 = hs0_u + (size_t)(t - 1) * H + tid;
            uint32_t v0 = ldg_relaxed_u32(p0);
            if (t >= 2) {
                const uint32_t* p1 = hs1_u + (size_t)(t - 2) * H + tid;
                uint32_t v1 = ldg_relaxed_u32(p1);
                while (v0 == CANARY || v1 == CANARY) {
                    if (v0 == CANARY) v0 = ldg_relaxed_u32(p0);
                    if (v1 == CANARY) v1 = ldg_relaxed_u32(p1);
                }
                sh_h1[tid] = __uint_as_float(v1);
            } else {
                while (v0 == CANARY) v0 = ldg_relaxed_u32(p0);
            }
            sh_h0[tid] = __uint_as_float(v0);
        }
        __syncthreads();                                   // S1: inputs staged

        // ---- layer0 dot: whh0 . h0(t-1) (+ wih0 . x(t) on s==0) ----
        if (t < S) {
            const uint4* h128 = reinterpret_cast<const uint4*>(&sh_h0[s * 64]);
            uint64_t a0 = 0, a1 = 0;
#pragma unroll
            for (int k = 0; k < 16; k++) {
                uint4 hv = h128[k];
                uint64_t hlo = ((uint64_t)hv.y << 32) | hv.x;
                uint64_t hhi = ((uint64_t)hv.w << 32) | hv.z;
                a0 = fma2_(whh0[2 * k], hlo, a0);
                a1 = fma2_(whh0[2 * k + 1], hhi, a1);
            }
            if (s == 0) {
                const uint64_t* x64 = reinterpret_cast<const uint64_t*>(sh_x);
#pragma unroll
                for (int k = 0; k < 4; k++) a0 = fma2_(wih0[k], x64[k], a0);
            }
            sh_part0[s * 64 + gL] = hsum2_(a0) + hsum2_(a1);
        }
        // ---- layer1 dot (time t-1): whh1 . h1(t-2) + wih1 . h0(t-1) ----
        if (t >= 1) {
            const uint4* h128 = reinterpret_cast<const uint4*>(&sh_h1[s * 64]);
            const uint4* x128 = reinterpret_cast<const uint4*>(&sh_h0[s * 64]);
            uint64_t a0 = 0, a1 = 0;
#pragma unroll
            for (int k = 0; k < 16; k++) {
                uint4 hv = h128[k];
                uint64_t hlo = ((uint64_t)hv.y << 32) | hv.x;
                uint64_t hhi = ((uint64_t)hv.w << 32) | hv.z;
                a0 = fma2_(whh1[2 * k], hlo, a0);
                a1 = fma2_(whh1[2 * k + 1], hhi, a1);
            }
#pragma unroll
            for (int k = 0; k < 16; k++) {
                uint4 xv = x128[k];
                uint64_t xlo = ((uint64_t)xv.y << 32) | xv.x;
                uint64_t xhi = ((uint64_t)xv.w << 32) | xv.z;
                a0 = fma2_(wih1[2 * k], xlo, a0);
                a1 = fma2_(wih1[2 * k + 1], xhi, a1);
            }
            sh_part1[s * 64 + gL] = hsum2_(a0) + hsum2_(a1);
        }
        __syncthreads();                                   // S2: partials ready

        // ---- owner tails (parallel: warp0 -> layer0, warp1 -> layer1) ----
        if (tid < CHUNK) {
            if (t < S) {
                float gate[4];
#pragma unroll
                for (int qq = 0; qq < 4; qq++) {
                    int gg = qq * CHUNK + tid;
                    gate[qq] = sh_part0[gg] + sh_part0[64 + gg] + sh_part0[128 + gg]
                             + sh_part0[192 + gg] + bias_q[qq];
                }
                float ig = fsig_(gate[0]);
                float fg = fsig_(gate[1]);
                float gv = ftanh_(gate[2]);
                float og = fsig_(gate[3]);
                c0 = fg * c0 + ig * gv;
                float hnew = og * ftanh_(c0);
                stg_relaxed_u32(hs0_u + (size_t)t * H + r * CHUNK + tid,
                                __float_as_uint(hnew));
            }
        } else if (tid >= 32 && tid < 32 + CHUNK) {
            if (t >= 1) {
                const int jj = tid - 32;
                float gate[4];
#pragma unroll
                for (int qq = 0; qq < 4; qq++) {
                    int gg = qq * CHUNK + jj;
                    gate[qq] = sh_part1[gg] + sh_part1[64 + gg] + sh_part1[128 + gg]
                             + sh_part1[192 + gg] + bias_q[qq];
                }
                float ig = fsig_(gate[0]);
                float fg = fsig_(gate[1]);
                float gv = ftanh_(gate[2]);
                float og = fsig_(gate[3]);
                c1 = fg * c1 + ig * gv;
                float hnew = og * ftanh_(c1);
                stg_relaxed_u32(hs1_u + (size_t)(t - 1) * H + r * CHUNK + jj,
                                __float_as_uint(hnew));
            }
        }
        // no third barrier: sh_part rewrite is gated by next tick's S1
    }
}

// ---------------- attention partials: split-S, split-softmax ---------------------
__global__ void __launch_bounds__(NT, 1) attn_part_kernel(
    const float* __restrict__ wq, const float* __restrict__ bq,
    const float* __restrict__ wk, const float* __restrict__ bk)
{
    const int cidx = blockIdx.x;
    const int bh   = blockIdx.y;
    const int b = bh >> 2, hd = bh & 3;
    const int tid = threadIdx.x;
    const float* h1b = g_hs1 + (size_t)b * S * H;
    const int base = cidx * SC;

    __shared__ float sh_last[H];
    __shared__ float sh_q[64];
    __shared__ float sh_qW[H];
    __shared__ float sh_qb;
    __shared__ float sc[SC];
    __shared__ float red[NT];

    sh_last[tid] = h1b[(size_t)(S - 1) * H + tid];
    __syncthreads();
    if (tid < 64) {
        int rq = hd * 64 + tid;
        float a = bq[rq];
#pragma unroll 4
        for (int k = 0; k < H; k++) a += wq[rq * H + k] * sh_last[k];
        sh_q[tid] = a;
    }
    __syncthreads();
    {
        float a = 0.f;
#pragma unroll 4
        for (int d = 0; d < 64; d++) a += sh_q[d] * wk[(hd * 64 + d) * H + tid];
        sh_qW[tid] = a;
    }
    if (tid == 0) {
        float a = 0.f;
        for (int d = 0; d < 64; d++) a += sh_q[d] * bk[hd * 64 + d];
        sh_qb = a;
    }
    __syncthreads();

    const float L2D = -0.07400058144377693f;   // log2(0.95)
    const int warp = tid >> 5, lane = tid & 31;
    float qr[8];
#pragma unroll
    for (int k = 0; k < 8; k++) qr[k] = sh_qW[lane * 8 + k];

#pragma unroll 2
    for (int i = warp; i < SC; i += 8) {
        int t = base + i;
        const float4* hr4 = reinterpret_cast<const float4*>(h1b + (size_t)t * H);
        float4 h0v = hr4[lane * 2], h1v = hr4[lane * 2 + 1];
        float a = qr[0]*h0v.x + qr[1]*h0v.y + qr[2]*h0v.z + qr[3]*h0v.w
                + qr[4]*h1v.x + qr[5]*h1v.y + qr[6]*h1v.z + qr[7]*h1v.w;
#pragma unroll
        for (int o = 16; o; o >>= 1) a += __shfl_xor_sync(0xffffffffu, a, o);
        if (lane == 0)
            sc[i] = (a + sh_qb) * 0.125f * exp2f((float)(S - 1 - t) * L2D);
    }
    __syncthreads();

    red[tid] = sc[tid]; __syncthreads();
    for (int o = NT / 2; o; o >>= 1) { if (tid < o) red[tid] = fmaxf(red[tid], red[tid + o]); __syncthreads(); }
    const float M = red[0]; __syncthreads();
    float e = expf(sc[tid] - M);
    sc[tid] = e;
    red[tid] = e; __syncthreads();
    for (int o = NT / 2; o; o >>= 1) { if (tid < o) red[tid] += red[tid + o]; __syncthreads(); }
    const float SUM = red[0];
    __syncthreads();

    float acc = 0.f;
#pragma unroll 8
    for (int i = 0; i < SC; i++) acc += sc[i] * h1b[(size_t)(base + i) * H + tid];
    g_ph[(size_t)(bh * NSPLIT + cidx) * H + tid] = acc;
    if (tid == 0) { g_pm[bh * NSPLIT + cidx] = M; g_ps[bh * NSPLIT + cidx] = SUM; }
}

// ---------------- tail: combine splits + V + O + heads (fused) -------------------
__global__ void __launch_bounds__(NT, 1) tail_kernel(
    const float* __restrict__ wv, const float* __restrict__ bv,
    const float* __restrict__ wo, const float* __restrict__ bo,
    const float* __restrict__ wm, const float* __restrict__ bm,
    const float* __restrict__ wvr, const float* __restrict__ bvr,
    float* __restrict__ out)
{
    const int b = blockIdx.x;
    const int tid = threadIdx.x;
    __shared__ float sh_w[NSPLIT];
    __shared__ float sh_hbar[H];
    __shared__ float sh_attn[H];
    __shared__ float sctx[H];
    __shared__ float sh_inv;

    for (int hd = 0; hd < 4; hd++) {
        const int bh = b * 4 + hd;
        if (tid == 0) {
            float M = -1e30f;
            for (int cI = 0; cI < NSPLIT; cI++) M = fmaxf(M, g_pm[bh * NSPLIT + cI]);
            float tot = 0.f;
            for (int cI = 0; cI < NSPLIT; cI++) {
                float w = expf(g_pm[bh * NSPLIT + cI] - M);
                sh_w[cI] = w;
                tot += w * g_ps[bh * NSPLIT + cI];
            }
            sh_inv = 1.f / tot;
        }
        __syncthreads();
        float a = 0.f;
#pragma unroll
        for (int cI = 0; cI < NSPLIT; cI++) a += sh_w[cI] * g_ph[(size_t)(bh * NSPLIT + cI) * H + tid];
        sh_hbar[tid] = a * sh_inv;
        __syncthreads();
        if (tid < 64) {
            int rv = hd * 64 + tid;
            float o = bv[rv];
#pragma unroll 4
            for (int k = 0; k < H; k++) o += wv[rv * H + k] * sh_hbar[k];
            sh_attn[hd * 64 + tid] = o;
        }
        __syncthreads();
    }

    float a = bo[tid];
#pragma unroll 4
    for (int k = 0; k < H; k++) a += wo[tid * H + k] * sh_attn[k];
    sctx[tid] = a;
    __syncthreads();
    if (tid < 5) {
        float m = bm[tid], lv = bvr[tid];
        for (int k = 0; k < H; k++) {
            m  += wm[tid * H + k] * sctx[k];
            lv += wvr[tid * H + k] * sctx[k];
        }
        out[b * 5 + tid] = m;
        out[B * 5 + b * 5 + tid] = lv;
    }
}

// ---------------- launch ----------------------------------------------------------
extern "C" void kernel_launch(void* const* d_in, const int* in_sizes, int n_in,
                              void* d_out, int out_size) {
    const float* x     = (const float*)d_in[0];
    const float* w_ih0 = (const float*)d_in[1];
    const float* w_hh0 = (const float*)d_in[2];
    const float* b_ih0 = (const float*)d_in[3];
    const float* b_hh0 = (const float*)d_in[4];
    const float* w_ih1 = (const float*)d_in[5];
    const float* w_hh1 = (const float*)d_in[6];
    const float* b_ih1 = (const float*)d_in[7];
    const float* b_hh1 = (const float*)d_in[8];
    const float* wq = (const float*)d_in[9];
    const float* bq = (const float*)d_in[10];
    const float* wk = (const float*)d_in[11];
    const float* bk = (const float*)d_in[12];
    const float* wv = (const float*)d_in[13];
    const float* bv = (const float*)d_in[14];
    const float* wo = (const float*)d_in[15];
    const float* bo = (const float*)d_in[16];
    const float* wm = (const float*)d_in[17];
    const float* bm = (const float*)d_in[18];
    const float* wvar = (const float*)d_in[19];
    const float* bvar = (const float*)d_in[20];
    float* out = (float*)d_out;

    dim3 grid_lstm(NC, B);   // 128 plain CTAs <= 148 SMs: co-resident, spin-safe
    fill_kernel<<<4096, 256>>>();                                        // #1: canary
    dummy_kernel<<<1, 32>>>();                                           // #2
    dummy_kernel<<<1, 32>>>();                                           // #3
    lstm_fused_kernel<<<grid_lstm, NT>>>(x, w_ih0, w_hh0, b_ih0, b_hh0,  // #4 (profiled)
                                         w_ih1, w_hh1, b_ih1, b_hh1);
    attn_part_kernel<<<dim3(NSPLIT, B * 4), NT>>>(wq, bq, wk, bk);       // #5
    tail_kernel<<<B, NT>>>(wv, bv, wo, bo, wm, bm, wvar, bvar, out);     // #6
}